// round 15
// baseline (speedup 1.0000x reference)
#include <cuda_runtime.h>
#include <math.h>

#define NTOT   65536
#define NGRAPH 128
#define NPG    512
#define EPG    4096
#define KPOOL  256
#define EDG    524288
#define IND    128
#define H1     256
#define H2     128

// ---------------- scratch (device globals; no allocation) ----------------
__device__ float    d_dinv[NTOT];
__device__ int      d_cntin[NTOT];
__device__ int      d_cstart[NTOT];
__device__ int      d_csr[EDG];
__device__ float    d_tx1[NTOT * IND];
__device__ float    d_h  [NTOT * H1];
__device__ float    d_z  [NTOT * H2];
__device__ float    d_as [NTOT];
__device__ float    d_ad [NTOT];
__device__ float    d_g  [NTOT * H2];
__device__ float    d_score[NTOT];
__device__ float    d_invpnorm;
// pre-split weights (hi/lo tf32), built once per launch
__device__ unsigned d_bhh[256 * H1], d_bhl[256 * H1];   // gemm_h B: rows 0-127 = w0, 128-255 = w1
__device__ unsigned d_bzh[256 * H2], d_bzl[256 * H2];   // gemm_z B: gat_w

// ---------------- helpers ----------------
__device__ __forceinline__ float lrelu(float x) { return x > 0.f ? x : 0.2f * x; }

__device__ __forceinline__ void tf32_split(float x, unsigned& hi, unsigned& lo) {
    unsigned h;
    asm("cvt.rna.tf32.f32 %0, %1;" : "=r"(h) : "f"(x));
    float hf = __uint_as_float(h);
    float lf = __fsub_rn(x, hf);
    unsigned l;
    asm("cvt.rna.tf32.f32 %0, %1;" : "=r"(l) : "f"(lf));
    hi = h; lo = l;
}

__device__ __forceinline__ void mma_tf32(float4& d, const unsigned* a, const unsigned* b) {
    asm volatile(
        "mma.sync.aligned.m16n8k8.row.col.f32.tf32.tf32.f32 "
        "{%0,%1,%2,%3}, {%4,%5,%6,%7}, {%8,%9}, {%0,%1,%2,%3};\n"
        : "+f"(d.x), "+f"(d.y), "+f"(d.z), "+f"(d.w)
        : "r"(a[0]), "r"(a[1]), "r"(a[2]), "r"(a[3]), "r"(b[0]), "r"(b[1]));
}

__device__ __forceinline__ unsigned smem_u32(const void* p) {
    return (unsigned)__cvta_generic_to_shared(p);
}
__device__ __forceinline__ void cp_async16(unsigned s, const void* g) {
    asm volatile("cp.async.cg.shared.global [%0], [%1], 16;" :: "r"(s), "l"(g));
}
__device__ __forceinline__ void cp_commit() {
    asm volatile("cp.async.commit_group;");
}
template<int N> __device__ __forceinline__ void cp_wait() {
    asm volatile("cp.async.wait_group %0;" :: "n"(N));
}

// ---------------- weight pre-split + as/ad zero-init + pnorm (once per launch) ----------
__global__ void k_split_w(const float* __restrict__ w0, const float* __restrict__ w1,
                          const float* __restrict__ gw, const float* __restrict__ p) {
    int i = blockIdx.x * blockDim.x + threadIdx.x;    // over 256*H1 = 65536
    {
        int k = i >> 8;                                // H1 = 256 cols
        float v = (k < 128) ? w0[i] : w1[i - 128 * H1];
        tf32_split(v, d_bhh[i], d_bhl[i]);
    }
    if (i < 256 * H2) {
        tf32_split(gw[i], d_bzh[i], d_bzl[i]);
    }
    d_as[i] = 0.f;
    d_ad[i] = 0.f;
    if (blockIdx.x == 0) {
        __shared__ float sh[128];
        int t = threadIdx.x;
        if (t < 128) { float v = p[t]; sh[t] = v * v; }
        __syncthreads();
        for (int o = 64; o > 0; o >>= 1) {
            if (t < o) sh[t] += sh[t + o];
            __syncthreads();
        }
        if (t == 0) d_invpnorm = 1.0f / sqrtf(sh[0]);
    }
}

// ---------------- fused per-graph CSR build ----------------
__global__ __launch_bounds__(512) void k_build(const int* __restrict__ row,
                                               const int* __restrict__ col) {
    __shared__ int sedge[EPG];
    __shared__ int sbuck[EPG];
    __shared__ int scnt[NPG];
    __shared__ int sdeg[NPG];
    __shared__ int sexcl[NPG];
    __shared__ int sfill[NPG];
    int b = blockIdx.x, t = threadIdx.x;
    int ebase = b * EPG, nbase = b * NPG;

    scnt[t] = 0; sdeg[t] = 0; sfill[t] = 0;
    __syncthreads();

    #pragma unroll
    for (int i = 0; i < EPG / NPG; i++) {
        int e = t + i * NPG;
        int rl = row[ebase + e] - nbase;
        int cl = col[ebase + e] - nbase;
        sedge[e] = (cl << 16) | rl;
        atomicAdd(&scnt[cl], 1);
        atomicAdd(&sdeg[rl], 1);
    }
    __syncthreads();

    int v = scnt[t];
    sexcl[t] = v;
    __syncthreads();
    for (int o = 1; o < NPG; o <<= 1) {
        int tmp = (t >= o) ? sexcl[t - o] : 0;
        __syncthreads();
        sexcl[t] += tmp;
        __syncthreads();
    }
    int excl = sexcl[t] - v;
    __syncthreads();
    sexcl[t] = excl;

    d_cstart[nbase + t] = ebase + excl;
    d_cntin[nbase + t]  = v;
    float dg = (float)sdeg[t];
    d_dinv[nbase + t] = dg > 0.f ? rsqrtf(fmaxf(dg, 1.0f)) : 0.f;
    __syncthreads();

    #pragma unroll
    for (int i = 0; i < EPG / NPG; i++) {
        int e = t + i * NPG;
        int pv = sedge[e];
        int cl = pv >> 16;
        int pos = atomicAdd(&sfill[cl], 1);
        sbuck[sexcl[cl] + pos] = (e << 9) | (pv & 511);
    }
    __syncthreads();

    int beg = sexcl[t], cnt = scnt[t];
    for (int i = beg + 1; i < beg + cnt; i++) {
        int key = sbuck[i];
        int j = i - 1;
        while (j >= beg && sbuck[j] > key) { sbuck[j + 1] = sbuck[j]; j--; }
        sbuck[j + 1] = key;
    }
    for (int j = 0; j < cnt; j++)
        d_csr[ebase + beg + j] = nbase + (sbuck[beg + j] & 511);
}

// ---------------- ChebConv gather (lane-parallel weights, edge-ascending sums) -------
__global__ void k_cheb_gather(const float* __restrict__ x) {
    int node = (blockIdx.x * blockDim.x + threadIdx.x) >> 5;
    int lane = threadIdx.x & 31;
    if (node >= NTOT) return;
    int beg = d_cstart[node], cnt = d_cntin[node];
    float dc = d_dinv[node];

    int   r0 = 0;
    float w0 = 0.f;
    if (lane < cnt) {
        r0 = __ldg(&d_csr[beg + lane]);
        w0 = -(__ldg(&d_dinv[r0]) * dc);
    }
    float4 acc = make_float4(0.f, 0.f, 0.f, 0.f);
    {
        int lim = min(cnt, 32);
        for (int k = 0; k < lim; k++) {
            float w = __shfl_sync(0xffffffffu, w0, k);
            int r   = __shfl_sync(0xffffffffu, r0, k);
            float4 xv = *(const float4*)(x + r * IND + lane * 4);
            acc.x = __fadd_rn(acc.x, __fmul_rn(w, xv.x));
            acc.y = __fadd_rn(acc.y, __fmul_rn(w, xv.y));
            acc.z = __fadd_rn(acc.z, __fmul_rn(w, xv.z));
            acc.w = __fadd_rn(acc.w, __fmul_rn(w, xv.w));
        }
    }
    for (int base = 32; base < cnt; base += 32) {
        int j = base + lane;
        int   rl = 0;
        float wl = 0.f;
        if (j < cnt) {
            rl = __ldg(&d_csr[beg + j]);
            wl = -(__ldg(&d_dinv[rl]) * dc);
        }
        int lim = min(cnt - base, 32);
        for (int k = 0; k < lim; k++) {
            float w = __shfl_sync(0xffffffffu, wl, k);
            int r   = __shfl_sync(0xffffffffu, rl, k);
            float4 xv = *(const float4*)(x + r * IND + lane * 4);
            acc.x = __fadd_rn(acc.x, __fmul_rn(w, xv.x));
            acc.y = __fadd_rn(acc.y, __fmul_rn(w, xv.y));
            acc.z = __fadd_rn(acc.z, __fmul_rn(w, xv.z));
            acc.w = __fadd_rn(acc.w, __fmul_rn(w, xv.w));
        }
    }
    *(float4*)(d_tx1 + node * IND + lane * 4) = acc;
}

// ---------------- tensor-core GEMMs : cp.async double-buffer (R11 layout) ----------------
// h = relu(x@W0 + tx1@W1 + b)
__global__ __launch_bounds__(256) void k_gemm_h_tc(const float* __restrict__ x,
                                                   const float* __restrict__ bias) {
    __shared__ float    As[2][128][20];
    __shared__ unsigned Bh[2][16][72];
    __shared__ unsigned Bl[2][16][72];
    int tid = threadIdx.x;
    int lane = tid & 31, wid = tid >> 5;
    int warp_m = wid & 3, warp_n = wid >> 2;
    int m0 = blockIdx.y * 128, n0 = blockIdx.x * 64;
    float4 dacc[2][4];
    #pragma unroll
    for (int i = 0; i < 2; i++)
        #pragma unroll
        for (int j = 0; j < 4; j++) dacc[i][j] = make_float4(0.f, 0.f, 0.f, 0.f);

    int ar0 = tid >> 2,          ak0 = (tid & 3) * 4;
    int ar1 = (tid + 256) >> 2,  ak1 = ((tid + 256) & 3) * 4;
    int br  = tid >> 4,          bn  = (tid & 15) * 4;

    auto issue_tile = [&](int buf, int k0) {
        const float* abase = (k0 < 128) ? (x + k0) : (d_tx1 + (k0 - 128));
        cp_async16(smem_u32(&As[buf][ar0][ak0]), abase + (m0 + ar0) * IND + ak0);
        cp_async16(smem_u32(&As[buf][ar1][ak1]), abase + (m0 + ar1) * IND + ak1);
        int bo = (k0 + br) * H1 + n0 + bn;
        cp_async16(smem_u32(&Bh[buf][br][bn]), d_bhh + bo);
        cp_async16(smem_u32(&Bl[buf][br][bn]), d_bhl + bo);
    };

    issue_tile(0, 0);
    cp_commit();

    for (int kt = 0; kt < 16; kt++) {
        int buf = kt & 1;
        if (kt < 15) { issue_tile(buf ^ 1, (kt + 1) * 16); cp_commit(); cp_wait<1>(); }
        else         { cp_wait<0>(); }
        __syncthreads();
        #pragma unroll
        for (int ks = 0; ks < 16; ks += 8) {
            int kr = ks + (lane & 3);
            unsigned bh[4][2], bl[4][2];
            int nc = warp_n * 32 + (lane >> 2);
            #pragma unroll
            for (int tn = 0; tn < 4; tn++) {
                int nn = nc + tn * 8;
                bh[tn][0] = Bh[buf][kr][nn]; bh[tn][1] = Bh[buf][kr + 4][nn];
                bl[tn][0] = Bl[buf][kr][nn]; bl[tn][1] = Bl[buf][kr + 4][nn];
            }
            int mr = warp_m * 32 + (lane >> 2);
            #pragma unroll
            for (int tm = 0; tm < 2; tm++) {
                int m = mr + tm * 16;
                unsigned ah[4], al[4];
                tf32_split(As[buf][m][kr],         ah[0], al[0]);
                tf32_split(As[buf][m + 8][kr],     ah[1], al[1]);
                tf32_split(As[buf][m][kr + 4],     ah[2], al[2]);
                tf32_split(As[buf][m + 8][kr + 4], ah[3], al[3]);
                #pragma unroll
                for (int tn = 0; tn < 4; tn++) mma_tf32(dacc[tm][tn], ah, bh[tn]);
                #pragma unroll
                for (int tn = 0; tn < 4; tn++) mma_tf32(dacc[tm][tn], ah, bl[tn]);
                #pragma unroll
                for (int tn = 0; tn < 4; tn++) mma_tf32(dacc[tm][tn], al, bh[tn]);
            }
        }
        __syncthreads();
    }
    #pragma unroll
    for (int tm = 0; tm < 2; tm++) {
        int rr = m0 + warp_m * 32 + tm * 16 + (lane >> 2);
        #pragma unroll
        for (int tn = 0; tn < 4; tn++) {
            int cc = n0 + warp_n * 32 + tn * 8 + (lane & 3) * 2;
            float bx = bias[cc], by = bias[cc + 1];
            float4 d = dacc[tm][tn];
            *(float2*)(d_h + rr * H1 + cc) =
                make_float2(fmaxf(d.x + bx, 0.f), fmaxf(d.y + by, 0.f));
            *(float2*)(d_h + (rr + 8) * H1 + cc) =
                make_float2(fmaxf(d.z + bx, 0.f), fmaxf(d.w + by, 0.f));
        }
    }
}

// z = h @ gat_w ; epilogue also accumulates a_s = z.asrc, a_d = z.adst
__global__ __launch_bounds__(256) void k_gemm_z_tc(const float* __restrict__ gas,
                                                   const float* __restrict__ gad) {
    __shared__ float    As[2][128][20];
    __shared__ unsigned Bh[2][16][72];
    __shared__ unsigned Bl[2][16][72];
    int tid = threadIdx.x;
    int lane = tid & 31, wid = tid >> 5;
    int warp_m = wid & 3, warp_n = wid >> 2;
    int m0 = blockIdx.y * 128, n0 = blockIdx.x * 64;
    float4 dacc[2][4];
    #pragma unroll
    for (int i = 0; i < 2; i++)
        #pragma unroll
        for (int j = 0; j < 4; j++) dacc[i][j] = make_float4(0.f, 0.f, 0.f, 0.f);

    int ar0 = tid >> 2,          ak0 = (tid & 3) * 4;
    int ar1 = (tid + 256) >> 2,  ak1 = ((tid + 256) & 3) * 4;
    int br  = tid >> 4,          bn  = (tid & 15) * 4;

    auto issue_tile = [&](int buf, int k0) {
        cp_async16(smem_u32(&As[buf][ar0][ak0]), d_h + (m0 + ar0) * H1 + k0 + ak0);
        cp_async16(smem_u32(&As[buf][ar1][ak1]), d_h + (m0 + ar1) * H1 + k0 + ak1);
        int bo = (k0 + br) * H2 + n0 + bn;
        cp_async16(smem_u32(&Bh[buf][br][bn]), d_bzh + bo);
        cp_async16(smem_u32(&Bl[buf][br][bn]), d_bzl + bo);
    };

    issue_tile(0, 0);
    cp_commit();

    for (int kt = 0; kt < 16; kt++) {
        int buf = kt & 1;
        if (kt < 15) { issue_tile(buf ^ 1, (kt + 1) * 16); cp_commit(); cp_wait<1>(); }
        else         { cp_wait<0>(); }
        __syncthreads();
        #pragma unroll
        for (int ks = 0; ks < 16; ks += 8) {
            int kr = ks + (lane & 3);
            unsigned bh[4][2], bl[4][2];
            int nc = warp_n * 32 + (lane >> 2);
            #pragma unroll
            for (int tn = 0; tn < 4; tn++) {
                int nn = nc + tn * 8;
                bh[tn][0] = Bh[buf][kr][nn]; bh[tn][1] = Bh[buf][kr + 4][nn];
                bl[tn][0] = Bl[buf][kr][nn]; bl[tn][1] = Bl[buf][kr + 4][nn];
            }
            int mr = warp_m * 32 + (lane >> 2);
            #pragma unroll
            for (int tm = 0; tm < 2; tm++) {
                int m = mr + tm * 16;
                unsigned ah[4], al[4];
                tf32_split(As[buf][m][kr],         ah[0], al[0]);
                tf32_split(As[buf][m + 8][kr],     ah[1], al[1]);
                tf32_split(As[buf][m][kr + 4],     ah[2], al[2]);
                tf32_split(As[buf][m + 8][kr + 4], ah[3], al[3]);
                #pragma unroll
                for (int tn = 0; tn < 4; tn++) mma_tf32(dacc[tm][tn], ah, bh[tn]);
                #pragma unroll
                for (int tn = 0; tn < 4; tn++) mma_tf32(dacc[tm][tn], ah, bl[tn]);
                #pragma unroll
                for (int tn = 0; tn < 4; tn++) mma_tf32(dacc[tm][tn], al, bh[tn]);
            }
        }
        __syncthreads();
    }
    #pragma unroll
    for (int tm = 0; tm < 2; tm++) {
        int rr = m0 + warp_m * 32 + tm * 16 + (lane >> 2);
        float s0 = 0.f, d0 = 0.f, s1 = 0.f, d1 = 0.f;
        #pragma unroll
        for (int tn = 0; tn < 4; tn++) {
            int cc = n0 + warp_n * 32 + tn * 8 + (lane & 3) * 2;
            float4 d = dacc[tm][tn];
            *(float2*)(d_z + rr * H2 + cc)       = make_float2(d.x, d.y);
            *(float2*)(d_z + (rr + 8) * H2 + cc) = make_float2(d.z, d.w);
            float a0 = __ldg(gas + cc), a1 = __ldg(gas + cc + 1);
            float b0 = __ldg(gad + cc), b1 = __ldg(gad + cc + 1);
            s0 += d.x * a0 + d.y * a1;  d0 += d.x * b0 + d.y * b1;
            s1 += d.z * a0 + d.w * a1;  d1 += d.z * b0 + d.w * b1;
        }
        #pragma unroll
        for (int o = 1; o < 4; o <<= 1) {
            s0 += __shfl_xor_sync(0xffffffffu, s0, o);
            d0 += __shfl_xor_sync(0xffffffffu, d0, o);
            s1 += __shfl_xor_sync(0xffffffffu, s1, o);
            d1 += __shfl_xor_sync(0xffffffffu, d1, o);
        }
        if ((lane & 3) == 0) {
            atomicAdd(&d_as[rr], s0);     atomicAdd(&d_ad[rr], d0);
            atomicAdd(&d_as[rr + 8], s1); atomicAdd(&d_ad[rr + 8], d1);
        }
    }
}

// ---------------- fused GAT softmax-aggregate + relu + score ----------------
__global__ void k_gat(const float* __restrict__ gb, const float* __restrict__ p) {
    int node = (blockIdx.x * blockDim.x + threadIdx.x) >> 5;
    int lane = threadIdx.x & 31;
    if (node >= NTOT) return;
    int beg = d_cstart[node], cnt = d_cntin[node];
    float ad_c = d_ad[node];
    float eself = lrelu(d_as[node] + ad_c);

    int   r0 = 0;
    float e0 = -3.402823e38f;
    if (lane < cnt) {
        r0 = __ldg(&d_csr[beg + lane]);
        e0 = lrelu(__ldg(&d_as[r0]) + ad_c);
    }
    float m = fmaxf(eself, e0);
    for (int j = lane + 32; j < cnt; j += 32) {
        int r = __ldg(&d_csr[beg + j]);
        m = fmaxf(m, lrelu(__ldg(&d_as[r]) + ad_c));
    }
    #pragma unroll
    for (int o = 16; o > 0; o >>= 1) m = fmaxf(m, __shfl_xor_sync(0xffffffffu, m, o));

    float ssum = 0.f;
    float p0 = (lane < cnt) ? expf(e0 - m) : 0.f;
    {
        int lim = min(cnt, 32);
        for (int k = 0; k < lim; k++)
            ssum = __fadd_rn(ssum, __shfl_sync(0xffffffffu, p0, k));
    }
    for (int base = 32; base < cnt; base += 32) {
        int j = base + lane;
        float pe = 0.f;
        if (j < cnt) {
            int r = __ldg(&d_csr[beg + j]);
            pe = expf(lrelu(__ldg(&d_as[r]) + ad_c) - m);
        }
        int lim = min(cnt - base, 32);
        for (int k = 0; k < lim; k++)
            ssum = __fadd_rn(ssum, __shfl_sync(0xffffffffu, pe, k));
    }
    float pself = expf(eself - m);
    ssum = __fadd_rn(ssum, pself);

    float4 acc = make_float4(0.f, 0.f, 0.f, 0.f);
    float a0 = p0 / ssum;
    {
        int lim = min(cnt, 32);
        for (int k = 0; k < lim; k++) {
            float alpha = __shfl_sync(0xffffffffu, a0, k);
            int r       = __shfl_sync(0xffffffffu, r0, k);
            float4 zv = *(const float4*)(d_z + r * H2 + lane * 4);
            acc.x = __fadd_rn(acc.x, __fmul_rn(alpha, zv.x));
            acc.y = __fadd_rn(acc.y, __fmul_rn(alpha, zv.y));
            acc.z = __fadd_rn(acc.z, __fmul_rn(alpha, zv.z));
            acc.w = __fadd_rn(acc.w, __fmul_rn(alpha, zv.w));
        }
    }
    for (int base = 32; base < cnt; base += 32) {
        int j = base + lane;
        float al = 0.f; int rl = 0;
        if (j < cnt) {
            rl = __ldg(&d_csr[beg + j]);
            al = expf(lrelu(__ldg(&d_as[rl]) + ad_c) - m) / ssum;
        }
        int lim = min(cnt - base, 32);
        for (int k = 0; k < lim; k++) {
            float alpha = __shfl_sync(0xffffffffu, al, k);
            int r       = __shfl_sync(0xffffffffu, rl, k);
            float4 zv = *(const float4*)(d_z + r * H2 + lane * 4);
            acc.x = __fadd_rn(acc.x, __fmul_rn(alpha, zv.x));
            acc.y = __fadd_rn(acc.y, __fmul_rn(alpha, zv.y));
            acc.z = __fadd_rn(acc.z, __fmul_rn(alpha, zv.z));
            acc.w = __fadd_rn(acc.w, __fmul_rn(alpha, zv.w));
        }
    }
    float aself = pself / ssum;
    float4 zc = *(const float4*)(d_z + node * H2 + lane * 4);
    float4 bv = *(const float4*)(gb + lane * 4);
    float4 g;
    g.x = fmaxf(__fadd_rn(acc.x, __fmul_rn(aself, zc.x)) + bv.x, 0.f);
    g.y = fmaxf(__fadd_rn(acc.y, __fmul_rn(aself, zc.y)) + bv.y, 0.f);
    g.z = fmaxf(__fadd_rn(acc.z, __fmul_rn(aself, zc.z)) + bv.z, 0.f);
    g.w = fmaxf(__fadd_rn(acc.w, __fmul_rn(aself, zc.w)) + bv.w, 0.f);
    *(float4*)(d_g + node * H2 + lane * 4) = g;
    float4 pv = *(const float4*)(p + lane * 4);
    float sc = g.x * pv.x + g.y * pv.y + g.z * pv.z + g.w * pv.w;
    #pragma unroll
    for (int o = 16; o > 0; o >>= 1) sc += __shfl_down_sync(0xffffffffu, sc, o);
    if (lane == 0) d_score[node] = tanhf(sc * d_invpnorm);
}

// ---------------- fused top-k pool (bitonic) + gated mean + MLP head ----------------
__global__ __launch_bounds__(256) void k_topk_mlp(const float* __restrict__ w1,
                                                  const float* __restrict__ b1,
                                                  const float* __restrict__ w2,
                                                  const float* __restrict__ b2,
                                                  float* __restrict__ out) {
    __shared__ float sv[NPG];
    __shared__ int   si[NPG];
    __shared__ float part[256];
    __shared__ float sgm[H2];
    __shared__ float red[256];
    int b = blockIdx.x, t = threadIdx.x;
    int base = b * NPG;
    sv[t]       = d_score[base + t];       si[t]       = t;
    sv[t + 256] = d_score[base + t + 256]; si[t + 256] = t + 256;
    __syncthreads();
    for (int k = 2; k <= NPG; k <<= 1) {
        for (int j = k >> 1; j > 0; j >>= 1) {
            #pragma unroll
            for (int s = 0; s < 2; s++) {
                int i = t + s * 256;
                int ixj = i ^ j;
                if (ixj > i) {
                    bool up = ((i & k) == 0);
                    float vi = sv[i], vj = sv[ixj];
                    bool sw = up ? (vi < vj) : (vi > vj);
                    if (sw) {
                        sv[i] = vj; sv[ixj] = vi;
                        int ti = si[i]; si[i] = si[ixj]; si[ixj] = ti;
                    }
                }
            }
            __syncthreads();
        }
    }
    int d = t & 127, half = t >> 7;
    float acc = 0.f;
    for (int j = half * 128; j < half * 128 + 128; j++)
        acc += d_g[(base + si[j]) * H2 + d] * sv[j];
    part[t] = acc;
    __syncthreads();
    if (t < 128) sgm[t] = (part[t] + part[t + 128]) * (1.0f / (float)KPOOL);
    __syncthreads();
    // MLP head
    float macc = b1[t];
    #pragma unroll 8
    for (int k = 0; k < H2; k++) macc += sgm[k] * w1[k * H1 + t];
    red[t] = fmaxf(macc, 0.f) * w2[t];
    __syncthreads();
    for (int o = 128; o > 0; o >>= 1) {
        if (t < o) red[t] += red[t + o];
        __syncthreads();
    }
    if (t == 0) out[b] = red[0] + b2[0];
}

// ---------------- launch ----------------
extern "C" void kernel_launch(void* const* d_in, const int* in_sizes, int n_in,
                              void* d_out, int out_size) {
    const float* x     = (const float*)d_in[0];
    const int*   ei    = (const int*)  d_in[1];
    const float* cw0   = (const float*)d_in[3];
    const float* cw1   = (const float*)d_in[4];
    const float* cb    = (const float*)d_in[5];
    const float* gw    = (const float*)d_in[6];
    const float* gas   = (const float*)d_in[7];
    const float* gad   = (const float*)d_in[8];
    const float* gb    = (const float*)d_in[9];
    const float* pp    = (const float*)d_in[10];
    const float* l1w   = (const float*)d_in[11];
    const float* l1b   = (const float*)d_in[12];
    const float* l2w   = (const float*)d_in[13];
    const float* l2b   = (const float*)d_in[14];
    float* out = (float*)d_out;

    int E = in_sizes[1] / 2;            // 524288
    const int* row = ei;
    const int* col = ei + E;

    k_split_w<<<256, 256>>>(cw0, cw1, gw, pp);
    k_build<<<NGRAPH, NPG>>>(row, col);

    k_cheb_gather<<<NTOT * 32 / 256, 256>>>(x);
    dim3 gh(H1 / 64, NTOT / 128);
    k_gemm_h_tc<<<gh, 256>>>(x, cb);

    dim3 gz(H2 / 64, NTOT / 128);
    k_gemm_z_tc<<<gz, 256>>>(gas, gad);
    k_gat<<<NTOT * 32 / 256, 256>>>(gb, pp);

    k_topk_mlp<<<NGRAPH, 256>>>(l1w, l1b, l2w, l2b, out);
}

// round 17
// speedup vs baseline: 1.0065x; 1.0065x over previous
#include <cuda_runtime.h>
#include <math.h>

#define NTOT   65536
#define NGRAPH 128
#define NPG    512
#define EPG    4096
#define KPOOL  256
#define EDG    524288
#define IND    128
#define H1     256
#define H2     128

// ---------------- scratch (device globals; no allocation) ----------------
__device__ float    d_dinv[NTOT];
__device__ int      d_cntin[NTOT];
__device__ int      d_cstart[NTOT];
__device__ int      d_csr[EDG];
__device__ float    d_tx1[NTOT * IND];
__device__ float    d_h  [NTOT * H1];
__device__ float    d_z  [NTOT * H2];
__device__ float    d_as [NTOT];
__device__ float    d_ad [NTOT];
__device__ float    d_g  [NTOT * H2];
__device__ float    d_score[NTOT];
__device__ float    d_invpnorm;
// pre-split weights (hi/lo tf32), built once per launch
__device__ unsigned d_bhh[256 * H1], d_bhl[256 * H1];   // gemm_h B: rows 0-127 = w0, 128-255 = w1
__device__ unsigned d_bzh[256 * H2], d_bzl[256 * H2];   // gemm_z B: gat_w

// ---------------- helpers ----------------
__device__ __forceinline__ float lrelu(float x) { return x > 0.f ? x : 0.2f * x; }

__device__ __forceinline__ void tf32_split(float x, unsigned& hi, unsigned& lo) {
    unsigned h;
    asm("cvt.rna.tf32.f32 %0, %1;" : "=r"(h) : "f"(x));
    float hf = __uint_as_float(h);
    float lf = __fsub_rn(x, hf);
    unsigned l;
    asm("cvt.rna.tf32.f32 %0, %1;" : "=r"(l) : "f"(lf));
    hi = h; lo = l;
}

__device__ __forceinline__ void mma_tf32(float4& d, const unsigned* a, const unsigned* b) {
    asm volatile(
        "mma.sync.aligned.m16n8k8.row.col.f32.tf32.tf32.f32 "
        "{%0,%1,%2,%3}, {%4,%5,%6,%7}, {%8,%9}, {%0,%1,%2,%3};\n"
        : "+f"(d.x), "+f"(d.y), "+f"(d.z), "+f"(d.w)
        : "r"(a[0]), "r"(a[1]), "r"(a[2]), "r"(a[3]), "r"(b[0]), "r"(b[1]));
}

__device__ __forceinline__ unsigned smem_u32(const void* p) {
    return (unsigned)__cvta_generic_to_shared(p);
}
__device__ __forceinline__ void cp_async16(unsigned s, const void* g) {
    asm volatile("cp.async.cg.shared.global [%0], [%1], 16;" :: "r"(s), "l"(g));
}
__device__ __forceinline__ void cp_commit() {
    asm volatile("cp.async.commit_group;");
}
template<int N> __device__ __forceinline__ void cp_wait() {
    asm volatile("cp.async.wait_group %0;" :: "n"(N));
}

// ---------------- fused per-graph CSR build + weight pre-split + pnorm ----------------
// 128 blocks x 512 threads; global thread id covers [0, 65536) = split domain exactly.
__global__ __launch_bounds__(512) void k_build(const int* __restrict__ row,
                                               const int* __restrict__ col,
                                               const float* __restrict__ w0,
                                               const float* __restrict__ w1,
                                               const float* __restrict__ gw,
                                               const float* __restrict__ p) {
    __shared__ int sedge[EPG];
    __shared__ int sbuck[EPG];
    __shared__ int scnt[NPG];
    __shared__ int sdeg[NPG];
    __shared__ int sexcl[NPG];
    __shared__ int sfill[NPG];
    int b = blockIdx.x, t = threadIdx.x;
    int ebase = b * EPG, nbase = b * NPG;

    // ---- independent prologue: weight pre-split, as/ad zero, pnorm ----
    {
        int i = b * NPG + t;                           // 0..65535
        int k = i >> 8;                                // H1 = 256 cols
        float v = (k < 128) ? w0[i] : w1[i - 128 * H1];
        tf32_split(v, d_bhh[i], d_bhl[i]);
        if (i < 256 * H2) tf32_split(gw[i], d_bzh[i], d_bzl[i]);
        d_as[i] = 0.f;
        d_ad[i] = 0.f;
    }
    if (b == 0 && t < 128) {
        // pnorm via warp reductions (threads 0-127 of block 0)
        float v = p[t];
        float s = v * v;
        #pragma unroll
        for (int o = 16; o > 0; o >>= 1) s += __shfl_down_sync(0xffffffffu, s, o);
        __shared__ float wsum[4];
        if ((t & 31) == 0) wsum[t >> 5] = s;
        __syncwarp();
        if (t == 0) {
            float tot = 0.f;
            // note: warp partials written before this read; ordered by syncthreads below?
            // use a simple fence: all 4 warps of t<128 wrote wsum before __syncthreads() in CSR part.
        }
        // finalize after the block-wide barrier below
        if (t == 0) { /* deferred */ }
        // store partials for post-barrier finalize
        (void)0;
    }

    scnt[t] = 0; sdeg[t] = 0; sfill[t] = 0;
    __syncthreads();

    // finalize pnorm after barrier (partials visible)
    if (b == 0 && t == 0) {
        // recompute serially over 128 elems (trivial, once per launch)
        float tot = 0.f;
        for (int i = 0; i < 128; i++) { float v = __ldg(p + i); tot = __fadd_rn(tot, __fmul_rn(v, v)); }
        // match prior pairwise-tree sum? pnorm feeds tanh(score * invpnorm); tiny
        // rounding differences here are ~1e-8 relative and uniform across all nodes
        // (ranking within a graph unaffected since same scalar scales every score).
        d_invpnorm = 1.0f / sqrtf(tot);
    }

    #pragma unroll
    for (int i = 0; i < EPG / NPG; i++) {
        int e = t + i * NPG;
        int rl = row[ebase + e] - nbase;
        int cl = col[ebase + e] - nbase;
        sedge[e] = (cl << 16) | rl;
        atomicAdd(&scnt[cl], 1);
        atomicAdd(&sdeg[rl], 1);
    }
    __syncthreads();

    int v = scnt[t];
    sexcl[t] = v;
    __syncthreads();
    for (int o = 1; o < NPG; o <<= 1) {
        int tmp = (t >= o) ? sexcl[t - o] : 0;
        __syncthreads();
        sexcl[t] += tmp;
        __syncthreads();
    }
    int excl = sexcl[t] - v;
    __syncthreads();
    sexcl[t] = excl;

    d_cstart[nbase + t] = ebase + excl;
    d_cntin[nbase + t]  = v;
    float dg = (float)sdeg[t];
    d_dinv[nbase + t] = dg > 0.f ? rsqrtf(fmaxf(dg, 1.0f)) : 0.f;
    __syncthreads();

    #pragma unroll
    for (int i = 0; i < EPG / NPG; i++) {
        int e = t + i * NPG;
        int pv = sedge[e];
        int cl = pv >> 16;
        int pos = atomicAdd(&sfill[cl], 1);
        sbuck[sexcl[cl] + pos] = (e << 9) | (pv & 511);
    }
    __syncthreads();

    int beg = sexcl[t], cnt = scnt[t];
    for (int i = beg + 1; i < beg + cnt; i++) {
        int key = sbuck[i];
        int j = i - 1;
        while (j >= beg && sbuck[j] > key) { sbuck[j + 1] = sbuck[j]; j--; }
        sbuck[j + 1] = key;
    }
    for (int j = 0; j < cnt; j++)
        d_csr[ebase + beg + j] = nbase + (sbuck[beg + j] & 511);
}

// ---------------- ChebConv gather (lane-parallel weights, edge-ascending sums) -------
__global__ void k_cheb_gather(const float* __restrict__ x) {
    int node = (blockIdx.x * blockDim.x + threadIdx.x) >> 5;
    int lane = threadIdx.x & 31;
    if (node >= NTOT) return;
    int beg = d_cstart[node], cnt = d_cntin[node];
    float dc = d_dinv[node];

    int   r0 = 0;
    float w0 = 0.f;
    if (lane < cnt) {
        r0 = __ldg(&d_csr[beg + lane]);
        w0 = -(__ldg(&d_dinv[r0]) * dc);
    }
    float4 acc = make_float4(0.f, 0.f, 0.f, 0.f);
    {
        int lim = min(cnt, 32);
        for (int k = 0; k < lim; k++) {
            float w = __shfl_sync(0xffffffffu, w0, k);
            int r   = __shfl_sync(0xffffffffu, r0, k);
            float4 xv = *(const float4*)(x + r * IND + lane * 4);
            acc.x = __fadd_rn(acc.x, __fmul_rn(w, xv.x));
            acc.y = __fadd_rn(acc.y, __fmul_rn(w, xv.y));
            acc.z = __fadd_rn(acc.z, __fmul_rn(w, xv.z));
            acc.w = __fadd_rn(acc.w, __fmul_rn(w, xv.w));
        }
    }
    for (int base = 32; base < cnt; base += 32) {
        int j = base + lane;
        int   rl = 0;
        float wl = 0.f;
        if (j < cnt) {
            rl = __ldg(&d_csr[beg + j]);
            wl = -(__ldg(&d_dinv[rl]) * dc);
        }
        int lim = min(cnt - base, 32);
        for (int k = 0; k < lim; k++) {
            float w = __shfl_sync(0xffffffffu, wl, k);
            int r   = __shfl_sync(0xffffffffu, rl, k);
            float4 xv = *(const float4*)(x + r * IND + lane * 4);
            acc.x = __fadd_rn(acc.x, __fmul_rn(w, xv.x));
            acc.y = __fadd_rn(acc.y, __fmul_rn(w, xv.y));
            acc.z = __fadd_rn(acc.z, __fmul_rn(w, xv.z));
            acc.w = __fadd_rn(acc.w, __fmul_rn(w, xv.w));
        }
    }
    *(float4*)(d_tx1 + node * IND + lane * 4) = acc;
}

// ---------------- tensor-core GEMMs : cp.async double-buffer (R11 layout) ----------------
// h = relu(x@W0 + tx1@W1 + b)
__global__ __launch_bounds__(256) void k_gemm_h_tc(const float* __restrict__ x,
                                                   const float* __restrict__ bias) {
    __shared__ float    As[2][128][20];
    __shared__ unsigned Bh[2][16][72];
    __shared__ unsigned Bl[2][16][72];
    int tid = threadIdx.x;
    int lane = tid & 31, wid = tid >> 5;
    int warp_m = wid & 3, warp_n = wid >> 2;
    int m0 = blockIdx.y * 128, n0 = blockIdx.x * 64;
    float4 dacc[2][4];
    #pragma unroll
    for (int i = 0; i < 2; i++)
        #pragma unroll
        for (int j = 0; j < 4; j++) dacc[i][j] = make_float4(0.f, 0.f, 0.f, 0.f);

    int ar0 = tid >> 2,          ak0 = (tid & 3) * 4;
    int ar1 = (tid + 256) >> 2,  ak1 = ((tid + 256) & 3) * 4;
    int br  = tid >> 4,          bn  = (tid & 15) * 4;

    auto issue_tile = [&](int buf, int k0) {
        const float* abase = (k0 < 128) ? (x + k0) : (d_tx1 + (k0 - 128));
        cp_async16(smem_u32(&As[buf][ar0][ak0]), abase + (m0 + ar0) * IND + ak0);
        cp_async16(smem_u32(&As[buf][ar1][ak1]), abase + (m0 + ar1) * IND + ak1);
        int bo = (k0 + br) * H1 + n0 + bn;
        cp_async16(smem_u32(&Bh[buf][br][bn]), d_bhh + bo);
        cp_async16(smem_u32(&Bl[buf][br][bn]), d_bhl + bo);
    };

    issue_tile(0, 0);
    cp_commit();

    for (int kt = 0; kt < 16; kt++) {
        int buf = kt & 1;
        if (kt < 15) { issue_tile(buf ^ 1, (kt + 1) * 16); cp_commit(); cp_wait<1>(); }
        else         { cp_wait<0>(); }
        __syncthreads();
        #pragma unroll
        for (int ks = 0; ks < 16; ks += 8) {
            int kr = ks + (lane & 3);
            unsigned bh[4][2], bl[4][2];
            int nc = warp_n * 32 + (lane >> 2);
            #pragma unroll
            for (int tn = 0; tn < 4; tn++) {
                int nn = nc + tn * 8;
                bh[tn][0] = Bh[buf][kr][nn]; bh[tn][1] = Bh[buf][kr + 4][nn];
                bl[tn][0] = Bl[buf][kr][nn]; bl[tn][1] = Bl[buf][kr + 4][nn];
            }
            int mr = warp_m * 32 + (lane >> 2);
            #pragma unroll
            for (int tm = 0; tm < 2; tm++) {
                int m = mr + tm * 16;
                unsigned ah[4], al[4];
                tf32_split(As[buf][m][kr],         ah[0], al[0]);
                tf32_split(As[buf][m + 8][kr],     ah[1], al[1]);
                tf32_split(As[buf][m][kr + 4],     ah[2], al[2]);
                tf32_split(As[buf][m + 8][kr + 4], ah[3], al[3]);
                #pragma unroll
                for (int tn = 0; tn < 4; tn++) mma_tf32(dacc[tm][tn], ah, bh[tn]);
                #pragma unroll
                for (int tn = 0; tn < 4; tn++) mma_tf32(dacc[tm][tn], ah, bl[tn]);
                #pragma unroll
                for (int tn = 0; tn < 4; tn++) mma_tf32(dacc[tm][tn], al, bh[tn]);
            }
        }
        __syncthreads();
    }
    #pragma unroll
    for (int tm = 0; tm < 2; tm++) {
        int rr = m0 + warp_m * 32 + tm * 16 + (lane >> 2);
        #pragma unroll
        for (int tn = 0; tn < 4; tn++) {
            int cc = n0 + warp_n * 32 + tn * 8 + (lane & 3) * 2;
            float bx = bias[cc], by = bias[cc + 1];
            float4 d = dacc[tm][tn];
            *(float2*)(d_h + rr * H1 + cc) =
                make_float2(fmaxf(d.x + bx, 0.f), fmaxf(d.y + by, 0.f));
            *(float2*)(d_h + (rr + 8) * H1 + cc) =
                make_float2(fmaxf(d.z + bx, 0.f), fmaxf(d.w + by, 0.f));
        }
    }
}

// z = h @ gat_w ; epilogue also accumulates a_s = z.asrc, a_d = z.adst
__global__ __launch_bounds__(256) void k_gemm_z_tc(const float* __restrict__ gas,
                                                   const float* __restrict__ gad) {
    __shared__ float    As[2][128][20];
    __shared__ unsigned Bh[2][16][72];
    __shared__ unsigned Bl[2][16][72];
    int tid = threadIdx.x;
    int lane = tid & 31, wid = tid >> 5;
    int warp_m = wid & 3, warp_n = wid >> 2;
    int m0 = blockIdx.y * 128, n0 = blockIdx.x * 64;
    float4 dacc[2][4];
    #pragma unroll
    for (int i = 0; i < 2; i++)
        #pragma unroll
        for (int j = 0; j < 4; j++) dacc[i][j] = make_float4(0.f, 0.f, 0.f, 0.f);

    int ar0 = tid >> 2,          ak0 = (tid & 3) * 4;
    int ar1 = (tid + 256) >> 2,  ak1 = ((tid + 256) & 3) * 4;
    int br  = tid >> 4,          bn  = (tid & 15) * 4;

    auto issue_tile = [&](int buf, int k0) {
        cp_async16(smem_u32(&As[buf][ar0][ak0]), d_h + (m0 + ar0) * H1 + k0 + ak0);
        cp_async16(smem_u32(&As[buf][ar1][ak1]), d_h + (m0 + ar1) * H1 + k0 + ak1);
        int bo = (k0 + br) * H2 + n0 + bn;
        cp_async16(smem_u32(&Bh[buf][br][bn]), d_bzh + bo);
        cp_async16(smem_u32(&Bl[buf][br][bn]), d_bzl + bo);
    };

    issue_tile(0, 0);
    cp_commit();

    for (int kt = 0; kt < 16; kt++) {
        int buf = kt & 1;
        if (kt < 15) { issue_tile(buf ^ 1, (kt + 1) * 16); cp_commit(); cp_wait<1>(); }
        else         { cp_wait<0>(); }
        __syncthreads();
        #pragma unroll
        for (int ks = 0; ks < 16; ks += 8) {
            int kr = ks + (lane & 3);
            unsigned bh[4][2], bl[4][2];
            int nc = warp_n * 32 + (lane >> 2);
            #pragma unroll
            for (int tn = 0; tn < 4; tn++) {
                int nn = nc + tn * 8;
                bh[tn][0] = Bh[buf][kr][nn]; bh[tn][1] = Bh[buf][kr + 4][nn];
                bl[tn][0] = Bl[buf][kr][nn]; bl[tn][1] = Bl[buf][kr + 4][nn];
            }
            int mr = warp_m * 32 + (lane >> 2);
            #pragma unroll
            for (int tm = 0; tm < 2; tm++) {
                int m = mr + tm * 16;
                unsigned ah[4], al[4];
                tf32_split(As[buf][m][kr],         ah[0], al[0]);
                tf32_split(As[buf][m + 8][kr],     ah[1], al[1]);
                tf32_split(As[buf][m][kr + 4],     ah[2], al[2]);
                tf32_split(As[buf][m + 8][kr + 4], ah[3], al[3]);
                #pragma unroll
                for (int tn = 0; tn < 4; tn++) mma_tf32(dacc[tm][tn], ah, bh[tn]);
                #pragma unroll
                for (int tn = 0; tn < 4; tn++) mma_tf32(dacc[tm][tn], ah, bl[tn]);
                #pragma unroll
                for (int tn = 0; tn < 4; tn++) mma_tf32(dacc[tm][tn], al, bh[tn]);
            }
        }
        __syncthreads();
    }
    #pragma unroll
    for (int tm = 0; tm < 2; tm++) {
        int rr = m0 + warp_m * 32 + tm * 16 + (lane >> 2);
        float s0 = 0.f, d0 = 0.f, s1 = 0.f, d1 = 0.f;
        #pragma unroll
        for (int tn = 0; tn < 4; tn++) {
            int cc = n0 + warp_n * 32 + tn * 8 + (lane & 3) * 2;
            float4 d = dacc[tm][tn];
            *(float2*)(d_z + rr * H2 + cc)       = make_float2(d.x, d.y);
            *(float2*)(d_z + (rr + 8) * H2 + cc) = make_float2(d.z, d.w);
            float a0 = __ldg(gas + cc), a1 = __ldg(gas + cc + 1);
            float b0 = __ldg(gad + cc), b1 = __ldg(gad + cc + 1);
            s0 += d.x * a0 + d.y * a1;  d0 += d.x * b0 + d.y * b1;
            s1 += d.z * a0 + d.w * a1;  d1 += d.z * b0 + d.w * b1;
        }
        #pragma unroll
        for (int o = 1; o < 4; o <<= 1) {
            s0 += __shfl_xor_sync(0xffffffffu, s0, o);
            d0 += __shfl_xor_sync(0xffffffffu, d0, o);
            s1 += __shfl_xor_sync(0xffffffffu, s1, o);
            d1 += __shfl_xor_sync(0xffffffffu, d1, o);
        }
        if ((lane & 3) == 0) {
            atomicAdd(&d_as[rr], s0);     atomicAdd(&d_ad[rr], d0);
            atomicAdd(&d_as[rr + 8], s1); atomicAdd(&d_ad[rr + 8], d1);
        }
    }
}

// ---------------- fused GAT softmax-aggregate + relu + score ----------------
__global__ void k_gat(const float* __restrict__ gb, const float* __restrict__ p) {
    int node = (blockIdx.x * blockDim.x + threadIdx.x) >> 5;
    int lane = threadIdx.x & 31;
    if (node >= NTOT) return;
    int beg = d_cstart[node], cnt = d_cntin[node];
    float ad_c = d_ad[node];
    float eself = lrelu(d_as[node] + ad_c);

    int   r0 = 0;
    float e0 = -3.402823e38f;
    if (lane < cnt) {
        r0 = __ldg(&d_csr[beg + lane]);
        e0 = lrelu(__ldg(&d_as[r0]) + ad_c);
    }
    float m = fmaxf(eself, e0);
    for (int j = lane + 32; j < cnt; j += 32) {
        int r = __ldg(&d_csr[beg + j]);
        m = fmaxf(m, lrelu(__ldg(&d_as[r]) + ad_c));
    }
    #pragma unroll
    for (int o = 16; o > 0; o >>= 1) m = fmaxf(m, __shfl_xor_sync(0xffffffffu, m, o));

    float ssum = 0.f;
    float p0 = (lane < cnt) ? expf(e0 - m) : 0.f;
    {
        int lim = min(cnt, 32);
        for (int k = 0; k < lim; k++)
            ssum = __fadd_rn(ssum, __shfl_sync(0xffffffffu, p0, k));
    }
    for (int base = 32; base < cnt; base += 32) {
        int j = base + lane;
        float pe = 0.f;
        if (j < cnt) {
            int r = __ldg(&d_csr[beg + j]);
            pe = expf(lrelu(__ldg(&d_as[r]) + ad_c) - m);
        }
        int lim = min(cnt - base, 32);
        for (int k = 0; k < lim; k++)
            ssum = __fadd_rn(ssum, __shfl_sync(0xffffffffu, pe, k));
    }
    float pself = expf(eself - m);
    ssum = __fadd_rn(ssum, pself);

    float4 acc = make_float4(0.f, 0.f, 0.f, 0.f);
    float a0 = p0 / ssum;
    {
        int lim = min(cnt, 32);
        for (int k = 0; k < lim; k++) {
            float alpha = __shfl_sync(0xffffffffu, a0, k);
            int r       = __shfl_sync(0xffffffffu, r0, k);
            float4 zv = *(const float4*)(d_z + r * H2 + lane * 4);
            acc.x = __fadd_rn(acc.x, __fmul_rn(alpha, zv.x));
            acc.y = __fadd_rn(acc.y, __fmul_rn(alpha, zv.y));
            acc.z = __fadd_rn(acc.z, __fmul_rn(alpha, zv.z));
            acc.w = __fadd_rn(acc.w, __fmul_rn(alpha, zv.w));
        }
    }
    for (int base = 32; base < cnt; base += 32) {
        int j = base + lane;
        float al = 0.f; int rl = 0;
        if (j < cnt) {
            rl = __ldg(&d_csr[beg + j]);
            al = expf(lrelu(__ldg(&d_as[rl]) + ad_c) - m) / ssum;
        }
        int lim = min(cnt - base, 32);
        for (int k = 0; k < lim; k++) {
            float alpha = __shfl_sync(0xffffffffu, al, k);
            int r       = __shfl_sync(0xffffffffu, rl, k);
            float4 zv = *(const float4*)(d_z + r * H2 + lane * 4);
            acc.x = __fadd_rn(acc.x, __fmul_rn(alpha, zv.x));
            acc.y = __fadd_rn(acc.y, __fmul_rn(alpha, zv.y));
            acc.z = __fadd_rn(acc.z, __fmul_rn(alpha, zv.z));
            acc.w = __fadd_rn(acc.w, __fmul_rn(alpha, zv.w));
        }
    }
    float aself = pself / ssum;
    float4 zc = *(const float4*)(d_z + node * H2 + lane * 4);
    float4 bv = *(const float4*)(gb + lane * 4);
    float4 g;
    g.x = fmaxf(__fadd_rn(acc.x, __fmul_rn(aself, zc.x)) + bv.x, 0.f);
    g.y = fmaxf(__fadd_rn(acc.y, __fmul_rn(aself, zc.y)) + bv.y, 0.f);
    g.z = fmaxf(__fadd_rn(acc.z, __fmul_rn(aself, zc.z)) + bv.z, 0.f);
    g.w = fmaxf(__fadd_rn(acc.w, __fmul_rn(aself, zc.w)) + bv.w, 0.f);
    *(float4*)(d_g + node * H2 + lane * 4) = g;
    float4 pv = *(const float4*)(p + lane * 4);
    float sc = g.x * pv.x + g.y * pv.y + g.z * pv.z + g.w * pv.w;
    #pragma unroll
    for (int o = 16; o > 0; o >>= 1) sc += __shfl_down_sync(0xffffffffu, sc, o);
    if (lane == 0) d_score[node] = tanhf(sc * d_invpnorm);
}

// ---------------- fused top-k pool (bitonic) + gated mean + MLP head ----------------
__global__ __launch_bounds__(256) void k_topk_mlp(const float* __restrict__ w1,
                                                  const float* __restrict__ b1,
                                                  const float* __restrict__ w2,
                                                  const float* __restrict__ b2,
                                                  float* __restrict__ out) {
    __shared__ float sv[NPG];
    __shared__ int   si[NPG];
    __shared__ float part[256];
    __shared__ float sgm[H2];
    __shared__ float red[256];
    int b = blockIdx.x, t = threadIdx.x;
    int base = b * NPG;
    sv[t]       = d_score[base + t];       si[t]       = t;
    sv[t + 256] = d_score[base + t + 256]; si[t + 256] = t + 256;
    __syncthreads();
    for (int k = 2; k <= NPG; k <<= 1) {
        for (int j = k >> 1; j > 0; j >>= 1) {
            #pragma unroll
            for (int s = 0; s < 2; s++) {
                int i = t + s * 256;
                int ixj = i ^ j;
                if (ixj > i) {
                    bool up = ((i & k) == 0);
                    float vi = sv[i], vj = sv[ixj];
                    bool sw = up ? (vi < vj) : (vi > vj);
                    if (sw) {
                        sv[i] = vj; sv[ixj] = vi;
                        int ti = si[i]; si[i] = si[ixj]; si[ixj] = ti;
                    }
                }
            }
            __syncthreads();
        }
    }
    int d = t & 127, half = t >> 7;
    float acc = 0.f;
    for (int j = half * 128; j < half * 128 + 128; j++)
        acc += d_g[(base + si[j]) * H2 + d] * sv[j];
    part[t] = acc;
    __syncthreads();
    if (t < 128) sgm[t] = (part[t] + part[t + 128]) * (1.0f / (float)KPOOL);
    __syncthreads();
    float macc = b1[t];
    #pragma unroll 8
    for (int k = 0; k < H2; k++) macc += sgm[k] * w1[k * H1 + t];
    red[t] = fmaxf(macc, 0.f) * w2[t];
    __syncthreads();
    for (int o = 128; o > 0; o >>= 1) {
        if (t < o) red[t] += red[t + o];
        __syncthreads();
    }
    if (t == 0) out[b] = red[0] + b2[0];
}

// ---------------- launch ----------------
extern "C" void kernel_launch(void* const* d_in, const int* in_sizes, int n_in,
                              void* d_out, int out_size) {
    const float* x     = (const float*)d_in[0];
    const int*   ei    = (const int*)  d_in[1];
    const float* cw0   = (const float*)d_in[3];
    const float* cw1   = (const float*)d_in[4];
    const float* cb    = (const float*)d_in[5];
    const float* gw    = (const float*)d_in[6];
    const float* gas   = (const float*)d_in[7];
    const float* gad   = (const float*)d_in[8];
    const float* gb    = (const float*)d_in[9];
    const float* pp    = (const float*)d_in[10];
    const float* l1w   = (const float*)d_in[11];
    const float* l1b   = (const float*)d_in[12];
    const float* l2w   = (const float*)d_in[13];
    const float* l2b   = (const float*)d_in[14];
    float* out = (float*)d_out;

    int E = in_sizes[1] / 2;            // 524288
    const int* row = ei;
    const int* col = ei + E;

    k_build<<<NGRAPH, NPG>>>(row, col, cw0, cw1, gw, pp);

    k_cheb_gather<<<NTOT * 32 / 256, 256>>>(x);
    dim3 gh(H1 / 64, NTOT / 128);
    k_gemm_h_tc<<<gh, 256>>>(x, cb);

    dim3 gz(H2 / 64, NTOT / 128);
    k_gemm_z_tc<<<gz, 256>>>(gas, gad);
    k_gat<<<NTOT * 32 / 256, 256>>>(gb, pp);

    k_topk_mlp<<<NGRAPH, 256>>>(l1w, l1b, l2w, l2b, out);
}